// round 9
// baseline (speedup 1.0000x reference)
#include <cuda_runtime.h>
#include <math.h>

#define Wd 512
#define Hd 512
#define Nimg 32
#define RAD 5
#define SW 32                 /* strip width (output cols per block) */
#define IN_W 42               /* input cols incl. halo */
#define IN_P 44               /* input ring col pitch */
#define RING 64               /* ring rows (power of 2) */
#define RM 63                 /* ring mask */
#define IPL (RING * IN_P)     /* input ring plane stride = 2816 */
#define HRP 33                /* hbuf row pitch */
#define HPL (RING * HRP)      /* hbuf plane stride = 2112 */
#define STEPS 8               /* 8 steps x 32 rows = 256 rows per block */
#define C2V 0.0009f           /* 0.03^2 */
#define NPART 1024            /* 16 x 2 x 32 blocks */

typedef unsigned long long u64;

__device__ __align__(16) float g_in[NPART];
__device__ __align__(16) float g_gr[NPART];
__device__ __align__(16) float g_ss[NPART];

// ---- packed f32x2 helpers (Blackwell FFMA2 path, PTX-only) ----
__device__ __forceinline__ u64 pk2(float a, float b) {
    u64 r; asm("mov.b64 %0, {%1, %2};" : "=l"(r) : "f"(a), "f"(b)); return r;
}
__device__ __forceinline__ void upk2(u64 v, float& a, float& b) {
    asm("mov.b64 {%0, %1}, %2;" : "=f"(a), "=f"(b) : "l"(v));
}
__device__ __forceinline__ u64 fma2(u64 a, u64 b, u64 c) {
    u64 d; asm("fma.rn.f32x2 %0, %1, %2, %3;" : "=l"(d) : "l"(a), "l"(b), "l"(c)); return d;
}
__device__ __forceinline__ u64 mul2(u64 a, u64 b) {
    u64 d; asm("mul.rn.f32x2 %0, %1, %2;" : "=l"(d) : "l"(a), "l"(b)); return d;
}
__device__ __forceinline__ u64 add2(u64 a, u64 b) {
    u64 d; asm("add.rn.f32x2 %0, %1, %2;" : "=l"(d) : "l"(a), "l"(b)); return d;
}

// Horizontal 11-tap pass for one row pair (absolute rows r0, r0+1) at hbuf col c.
__device__ __forceinline__ void hpass_pair(
    const float* __restrict__ sv, const float* __restrict__ si,
    const float* __restrict__ sg, float* __restrict__ hbuf,
    const u64* __restrict__ wp, int r0, int c)
{
    const int p0 = (r0 & RM) * IN_P + c;
    const int p1 = ((r0 + 1) & RM) * IN_P + c;
    const float* bg0 = sg + p0; const float* bg1 = sg + p1;
    const float* bi0 = si + p0; const float* bi1 = si + p1;
    const float* bv0 = sv + p0; const float* bv1 = sv + p1;
    u64 a0 = 0, a1 = 0, a2 = 0, a3 = 0, a4 = 0, a5 = 0, a6 = 0, a7 = 0;
    #pragma unroll
    for (int k = 0; k < 11; k++) {
        u64 z2 = pk2(bg0[k], bg1[k]);
        u64 q2 = pk2(bi0[k], bi1[k]);
        u64 v2 = pk2(bv0[k], bv1[k]);
        u64 w2 = wp[k];
        u64 t  = mul2(w2, z2);
        u64 tq = mul2(w2, q2);
        u64 tv = mul2(w2, v2);
        a0 = add2(a0, t);           // gen
        a1 = add2(a1, tq);          // ir
        a2 = add2(a2, tv);          // vis
        a3 = fma2(t,  z2, a3);      // gen*gen
        a4 = fma2(tq, q2, a4);      // ir*ir
        a5 = fma2(tv, v2, a5);      // vis*vis
        a6 = fma2(t,  q2, a6);      // gen*ir
        a7 = fma2(t,  v2, a7);      // gen*vis
    }
    float lo, hi;
    float* h0 = hbuf + (r0 & RM) * HRP + c;
    float* h1 = hbuf + ((r0 + 1) & RM) * HRP + c;
    upk2(a0, lo, hi); h0[0*HPL] = lo; h1[0*HPL] = hi;
    upk2(a1, lo, hi); h0[1*HPL] = lo; h1[1*HPL] = hi;
    upk2(a2, lo, hi); h0[2*HPL] = lo; h1[2*HPL] = hi;
    upk2(a3, lo, hi); h0[3*HPL] = lo; h1[3*HPL] = hi;
    upk2(a4, lo, hi); h0[4*HPL] = lo; h1[4*HPL] = hi;
    upk2(a5, lo, hi); h0[5*HPL] = lo; h1[5*HPL] = hi;
    upk2(a6, lo, hi); h0[6*HPL] = lo; h1[6*HPL] = hi;
    upk2(a7, lo, hi); h0[7*HPL] = lo; h1[7*HPL] = hi;
}

// Sobel over 4 consecutive absolute rows (y0..y0+3) of ring-resident image s,
// at output col x (ring col x+5). Shares the 6x3 halo loads.
__device__ __forceinline__ void sobel4r(const float* __restrict__ s, int y0, int x,
                                        float out[4]) {
    float a[6][3];
    #pragma unroll
    for (int rr = 0; rr < 6; rr++) {
        const float* row = s + ((y0 + rr - 1) & RM) * IN_P + (x + RAD - 1);
        a[rr][0] = row[0]; a[rr][1] = row[1]; a[rr][2] = row[2];
    }
    #pragma unroll
    for (int i = 0; i < 4; i++) {
        float gx = (a[i][2] - a[i][0]) + 2.0f * (a[i+1][2] - a[i+1][0]) + (a[i+2][2] - a[i+2][0]);
        float gy = (a[i][0] + 2.0f * a[i][1] + a[i][2]) - (a[i+2][0] + 2.0f * a[i+2][1] + a[i+2][2]);
        out[i] = fabsf(gx) + fabsf(gy);
    }
}

__global__ __launch_bounds__(256, 2)
void fused_kernel(const float* __restrict__ vis,
                  const float* __restrict__ ir,
                  const float* __restrict__ gen)
{
    __shared__ float gwin[11];
    __shared__ float red[8][3];
    extern __shared__ float smem[];
    float* sv   = smem;                // vis ring  [RING][IN_P]
    float* si   = sv + IPL;            // ir ring
    float* sg   = si + IPL;            // gen ring
    float* hbuf = sg + IPL;            // 8 planes x [RING][HRP]

    const int tid = threadIdx.x;

    if (tid == 0) {
        float raw[11]; float s = 0.0f;
        #pragma unroll
        for (int i = 0; i < 11; i++) {
            float d = (float)(i - 5);
            raw[i] = expf(-(d * d) / 4.5f);
            s += raw[i];
        }
        #pragma unroll
        for (int i = 0; i < 11; i++) gwin[i] = raw[i] / s;
    }

    const int n   = blockIdx.z;
    const int tx0 = blockIdx.x * SW;
    const int ys  = blockIdx.y * (STEPS * 32);     // first output row of strip
    const long base = (long)n * (Hd * Wd);
    const float* pv = vis + base;
    const float* pi = ir  + base;
    const float* pg = gen + base;

    // ---- Prime: load input rows ys-5 .. ys+4 (10 rows x 42 cols) ----
    for (int idx = tid; idx < 10 * IN_W; idx += 256) {
        int r = idx / IN_W, col = idx - r * IN_W;
        int gy = ys - RAD + r;
        int gx = tx0 + col - RAD;
        bool ok = ((unsigned)gy < (unsigned)Hd) && ((unsigned)gx < (unsigned)Wd);
        int o = gy * Wd + gx;
        int so = (gy & RM) * IN_P + col;
        sv[so] = ok ? pv[o] : 0.0f;
        si[so] = ok ? pi[o] : 0.0f;
        sg[so] = ok ? pg[o] : 0.0f;
    }
    __syncthreads();

    // Pre-packed window weights
    u64 wp[11];
    #pragma unroll
    for (int k = 0; k < 11; k++) { float w = gwin[k]; wp[k] = pk2(w, w); }

    // ---- Prime hbuf rows ys-5 .. ys+4 (5 row pairs x 32 cols = 160 tasks) ----
    if (tid < 160) {
        int rp = tid >> 5, c = tid & 31;
        hpass_pair(sv, si, sg, hbuf, wp, ys - RAD + 2 * rp, c);
    }

    float acc_in = 0.0f, acc_grad = 0.0f, acc_ssim = 0.0f;
    const int x = tid & 31;

    for (int s = 0; s < STEPS; s++) {
        const int yo = ys + 32 * s;                 // output rows yo..yo+31
        __syncthreads();   // prior phase3 reads done before ring overwrite

        // ---- Load input rows yo+5 .. yo+36 (32 rows x 42 cols) ----
        for (int idx = tid; idx < 32 * IN_W; idx += 256) {
            int r = idx / IN_W, col = idx - r * IN_W;
            int gy = yo + RAD + r;                  // >= 5 always
            int gx = tx0 + col - RAD;
            bool ok = (gy < Hd) && ((unsigned)gx < (unsigned)Wd);
            int o = gy * Wd + gx;
            int so = (gy & RM) * IN_P + col;
            sv[so] = ok ? pv[o] : 0.0f;
            si[so] = ok ? pi[o] : 0.0f;
            sg[so] = ok ? pg[o] : 0.0f;
        }
        __syncthreads();

        // ---- Horizontal pass: hbuf rows yo+5 .. yo+36 (16 pairs x 32 = 512 tasks) ----
        {
            int idx = tid;
            int rp = idx >> 5, c = idx & 31;
            hpass_pair(sv, si, sg, hbuf, wp, yo + RAD + 2 * rp, c);
            idx = tid + 256;
            rp = idx >> 5; c = idx & 31;
            hpass_pair(sv, si, sg, hbuf, wp, yo + RAD + 2 * rp, c);
        }
        __syncthreads();

        // ---- Vertical pass + SSIM + Sobel + L1 for rows y0..y0+3 ----
        const int y0 = yo + (tid >> 5) * 4;

        u64 acc[4][4];
        #pragma unroll
        for (int i = 0; i < 4; i++)
            #pragma unroll
            for (int p = 0; p < 4; p++) acc[i][p] = 0;

        #pragma unroll
        for (int t = 0; t < 14; t++) {
            const float* hr = hbuf + ((y0 - RAD + t) & RM) * HRP + x;
            u64 l0 = pk2(hr[0*HPL], hr[1*HPL]);   // (mu_gen, mu_ir)
            u64 l1 = pk2(hr[2*HPL], hr[3*HPL]);   // (mu_vis, gg)
            u64 l2 = pk2(hr[4*HPL], hr[5*HPL]);   // (ii, vv)
            u64 l3 = pk2(hr[6*HPL], hr[7*HPL]);   // (gi, gv)
            const int ilo = (t > 10) ? (t - 10) : 0;
            const int ihi = (t < 3) ? t : 3;
            #pragma unroll
            for (int i = 0; i < 4; i++) {
                if (i >= ilo && i <= ihi) {
                    u64 w2 = wp[t - i];
                    acc[i][0] = fma2(w2, l0, acc[i][0]);
                    acc[i][1] = fma2(w2, l1, acc[i][1]);
                    acc[i][2] = fma2(w2, l2, acc[i][2]);
                    acc[i][3] = fma2(w2, l3, acc[i][3]);
                }
            }
        }

        #pragma unroll
        for (int i = 0; i < 4; i++) {
            float mu1, mu2, mu3, mgg, mii, mvv, mgi, mgv;
            upk2(acc[i][0], mu1, mu2);
            upk2(acc[i][1], mu3, mgg);
            upk2(acc[i][2], mii, mvv);
            upk2(acc[i][3], mgi, mgv);
            float s1q = mgg - mu1 * mu1;
            float s2q = mii - mu2 * mu2;
            float s3q = mvv - mu3 * mu3;
            float s12 = mgi - mu1 * mu2;
            float s13 = mgv - mu1 * mu3;
            float x2 = sqrtf(s2q), x3 = sqrtf(s3q);
            float map12 = (2.0f * s12 + C2V) / (s1q + s2q + C2V);
            float map13 = (2.0f * s13 + C2V) / (s1q + s3q + C2V);
            // NaN (sqrt of tiny-negative variance) -> cmp false -> map13, matches jnp.where
            acc_ssim += (fabsf(x2) >= fabsf(x3)) ? map12 : map13;
        }

        {
            float gv[4], gi[4], gg[4];
            sobel4r(sv, y0, x, gv);
            sobel4r(si, y0, x, gi);
            sobel4r(sg, y0, x, gg);
            #pragma unroll
            for (int i = 0; i < 4; i++) {
                int cc = ((y0 + i) & RM) * IN_P + (x + RAD);
                acc_in   += fabsf(sg[cc] - fmaxf(sv[cc], si[cc]));
                acc_grad += fabsf(gg[i] - fmaxf(gv[i], gi[i]));
            }
        }
    }

    // ---- deterministic block reduction ----
    #pragma unroll
    for (int off = 16; off; off >>= 1) {
        acc_in   += __shfl_down_sync(0xffffffffu, acc_in,   off);
        acc_grad += __shfl_down_sync(0xffffffffu, acc_grad, off);
        acc_ssim += __shfl_down_sync(0xffffffffu, acc_ssim, off);
    }
    int warp = tid >> 5, lane = tid & 31;
    if (lane == 0) { red[warp][0] = acc_in; red[warp][1] = acc_grad; red[warp][2] = acc_ssim; }
    __syncthreads();
    if (tid == 0) {
        float a = 0, b = 0, c = 0;
        #pragma unroll
        for (int w = 0; w < 8; w++) { a += red[w][0]; b += red[w][1]; c += red[w][2]; }
        int bId = (blockIdx.z * 2 + blockIdx.y) * 16 + blockIdx.x;
        g_in[bId] = a;
        g_gr[bId] = b;
        g_ss[bId] = c;
    }
}

__global__ __launch_bounds__(256)
void finalize_kernel(float* __restrict__ out)
{
    __shared__ float r0[8], r1[8], r2[8];
    const int tid = threadIdx.x;
    const float4* p0 = (const float4*)g_in;    // 256 float4 per array
    const float4* p1 = (const float4*)g_gr;
    const float4* p2 = (const float4*)g_ss;
    float4 v0 = p0[tid], v1 = p1[tid], v2 = p2[tid];
    float a0 = (v0.x + v0.y) + (v0.z + v0.w);
    float a1 = (v1.x + v1.y) + (v1.z + v1.w);
    float a2 = (v2.x + v2.y) + (v2.z + v2.w);
    #pragma unroll
    for (int off = 16; off; off >>= 1) {
        a0 += __shfl_down_sync(0xffffffffu, a0, off);
        a1 += __shfl_down_sync(0xffffffffu, a1, off);
        a2 += __shfl_down_sync(0xffffffffu, a2, off);
    }
    int warp = tid >> 5, lane = tid & 31;
    if (lane == 0) { r0[warp] = a0; r1[warp] = a1; r2[warp] = a2; }
    __syncthreads();
    if (tid == 0) {
        double t0 = 0, t1 = 0, t2 = 0;
        #pragma unroll
        for (int w = 0; w < 8; w++) {
            t0 += (double)r0[w]; t1 += (double)r1[w]; t2 += (double)r2[w];
        }
        const double tot = (double)Nimg * Hd * Wd;   // 8388608
        double loss_in   = 1.5 * t0 / tot;
        double loss_grad = t1 / tot;
        double ssim_mean = t2 / tot;
        out[0] = (float)loss_in;
        out[1] = (float)(0.5 * (1.0 - ssim_mean) + loss_grad);
    }
}

extern "C" void kernel_launch(void* const* d_in, const int* in_sizes, int n_in,
                              void* d_out, int out_size)
{
    const float* vis = (const float*)d_in[0];
    const float* ir  = (const float*)d_in[1];
    const float* gen = (const float*)d_in[2];
    float* out = (float*)d_out;

    // 3 input rings (64x44) + 8 hbuf planes (64x33), all float
    const int SMEM_BYTES = (3 * IPL + 8 * HPL) * (int)sizeof(float);   // 101376
    cudaFuncSetAttribute(fused_kernel, cudaFuncAttributeMaxDynamicSharedMemorySize, SMEM_BYTES);
    cudaFuncSetAttribute(fused_kernel, cudaFuncAttributePreferredSharedMemoryCarveout,
                         cudaSharedmemCarveoutMaxShared);

    dim3 grid(16, 2, 32);   // col strip, half-height, image
    fused_kernel<<<grid, 256, SMEM_BYTES>>>(vis, ir, gen);
    finalize_kernel<<<1, 256>>>(out);
}

// round 10
// speedup vs baseline: 1.1712x; 1.1712x over previous
#include <cuda_runtime.h>
#include <math.h>

#define Wd 512
#define Hd 512
#define Nimg 32
#define TILE 32
#define RAD 5
#define IN_T 42               /* TILE + 2*RAD */
#define IN_P 44               /* padded pitch for input tiles */
#define HP 33                 /* pitch for horizontal-pass buffer */
#define PL (IN_T * HP)        /* plane stride in hbuf */
#define C2V 0.0009f           /* 0.03^2 */
#define NBLOCKS (16*16*32)    /* 8192 */

typedef unsigned long long u64;

__device__ __align__(16) float g_in[NBLOCKS];
__device__ __align__(16) float g_gr[NBLOCKS];
__device__ __align__(16) float g_ss[NBLOCKS];

// ---- packed f32x2 helpers (Blackwell FFMA2 path, PTX-only) ----
__device__ __forceinline__ u64 pk2(float a, float b) {
    u64 r; asm("mov.b64 %0, {%1, %2};" : "=l"(r) : "f"(a), "f"(b)); return r;
}
__device__ __forceinline__ void upk2(u64 v, float& a, float& b) {
    asm("mov.b64 {%0, %1}, %2;" : "=f"(a), "=f"(b) : "l"(v));
}
__device__ __forceinline__ u64 fma2(u64 a, u64 b, u64 c) {
    u64 d; asm("fma.rn.f32x2 %0, %1, %2, %3;" : "=l"(d) : "l"(a), "l"(b), "l"(c)); return d;
}
__device__ __forceinline__ u64 mul2(u64 a, u64 b) {
    u64 d; asm("mul.rn.f32x2 %0, %1, %2;" : "=l"(d) : "l"(a), "l"(b)); return d;
}
__device__ __forceinline__ u64 add2(u64 a, u64 b) {
    u64 d; asm("add.rn.f32x2 %0, %1, %2;" : "=l"(d) : "l"(a), "l"(b)); return d;
}

// Sobel over 4 consecutive rows of one column, sharing the 6x3 halo loads.
__device__ __forceinline__ void sobel4(const float* __restrict__ s, int y0, int x,
                                       float out[4]) {
    float a[6][3];
    #pragma unroll
    for (int rr = 0; rr < 6; rr++) {
        const float* row = s + (y0 + rr + RAD - 1) * IN_P + (x + RAD - 1);
        a[rr][0] = row[0]; a[rr][1] = row[1]; a[rr][2] = row[2];
    }
    #pragma unroll
    for (int i = 0; i < 4; i++) {
        float gx = (a[i][2] - a[i][0]) + 2.0f * (a[i+1][2] - a[i+1][0]) + (a[i+2][2] - a[i+2][0]);
        float gy = (a[i][0] + 2.0f * a[i][1] + a[i][2]) - (a[i+2][0] + 2.0f * a[i+2][1] + a[i+2][2]);
        out[i] = fabsf(gx) + fabsf(gy);
    }
}

__global__ __launch_bounds__(256, 3)
void fused_kernel(const float* __restrict__ vis,
                  const float* __restrict__ ir,
                  const float* __restrict__ gen)
{
    __shared__ float gwin[11];
    __shared__ float red[8][3];
    extern __shared__ float smem[];
    float* sv   = smem;                       // vis tile  [IN_T][IN_P]
    float* si   = sv + IN_T * IN_P;           // ir tile
    float* sg   = si + IN_T * IN_P;           // gen tile
    float* hbuf = sg + IN_T * IN_P;           // 8 planes x [IN_T][HP]

    const int tid = threadIdx.x;

    if (tid == 0) {
        float raw[11]; float s = 0.0f;
        #pragma unroll
        for (int i = 0; i < 11; i++) {
            float d = (float)(i - 5);
            raw[i] = expf(-(d * d) / 4.5f);
            s += raw[i];
        }
        #pragma unroll
        for (int i = 0; i < 11; i++) gwin[i] = raw[i] / s;
    }

    const int n   = blockIdx.z;
    const int tx0 = blockIdx.x * TILE;
    const int ty0 = blockIdx.y * TILE;
    const long base = (long)n * (Hd * Wd);
    const float* pv = vis + base;
    const float* pi = ir  + base;
    const float* pg = gen + base;

    // ---- Phase 1: load 42x42 halo tiles (zero-padded outside image) ----
    for (int idx = tid; idx < IN_T * IN_T; idx += 256) {
        int r = idx / IN_T, c = idx - r * IN_T;
        int gy = ty0 + r - RAD, gx = tx0 + c - RAD;
        bool ok = ((unsigned)gy < (unsigned)Hd) && ((unsigned)gx < (unsigned)Wd);
        int o = gy * Wd + gx;
        sv[r * IN_P + c] = ok ? pv[o] : 0.0f;
        si[r * IN_P + c] = ok ? pi[o] : 0.0f;
        sg[r * IN_P + c] = ok ? pg[o] : 0.0f;
    }
    __syncthreads();

    // Pre-packed duplicated window weights (register-resident, static indexing)
    u64 wp[11];
    #pragma unroll
    for (int k = 0; k < 11; k++) { float w = gwin[k]; wp[k] = pk2(w, w); }

    // ---- Phase 2: horizontal Gaussian, 2 rows/thread packed into f32x2 ----
    // tasks: 21 row-pairs x 32 cols = 672
    for (int idx = tid; idx < 672; idx += 256) {
        int rp = idx >> 5;          // 0..20
        int c  = idx & 31;
        const float* bg = sg + (2 * rp) * IN_P + c;
        const float* bi = si + (2 * rp) * IN_P + c;
        const float* bv = sv + (2 * rp) * IN_P + c;
        u64 a0 = 0, a1 = 0, a2 = 0, a3 = 0, a4 = 0, a5 = 0, a6 = 0, a7 = 0;
        #pragma unroll
        for (int k = 0; k < 11; k++) {
            u64 z2 = pk2(bg[k], bg[k + IN_P]);
            u64 q2 = pk2(bi[k], bi[k + IN_P]);
            u64 v2 = pk2(bv[k], bv[k + IN_P]);
            u64 w2 = wp[k];
            u64 t  = mul2(w2, z2);
            u64 tq = mul2(w2, q2);
            u64 tv = mul2(w2, v2);
            a0 = add2(a0, t);           // gen
            a1 = add2(a1, tq);          // ir
            a2 = add2(a2, tv);          // vis
            a3 = fma2(t,  z2, a3);      // gen*gen
            a4 = fma2(tq, q2, a4);      // ir*ir
            a5 = fma2(tv, v2, a5);      // vis*vis
            a6 = fma2(t,  q2, a6);      // gen*ir
            a7 = fma2(t,  v2, a7);      // gen*vis
        }
        float lo, hi;
        float* h = hbuf + (2 * rp) * HP + c;
        upk2(a0, lo, hi); h[0*PL] = lo; h[0*PL + HP] = hi;
        upk2(a1, lo, hi); h[1*PL] = lo; h[1*PL + HP] = hi;
        upk2(a2, lo, hi); h[2*PL] = lo; h[2*PL + HP] = hi;
        upk2(a3, lo, hi); h[3*PL] = lo; h[3*PL + HP] = hi;
        upk2(a4, lo, hi); h[4*PL] = lo; h[4*PL + HP] = hi;
        upk2(a5, lo, hi); h[5*PL] = lo; h[5*PL + HP] = hi;
        upk2(a6, lo, hi); h[6*PL] = lo; h[6*PL + HP] = hi;
        upk2(a7, lo, hi); h[7*PL] = lo; h[7*PL + HP] = hi;
    }
    __syncthreads();

    // ---- Phase 3: vertical pass, 4 output rows per thread, field-paired FFMA2 ----
    const int x  = tid & 31;
    const int y0 = (tid >> 5) * 4;

    u64 acc[4][4];
    #pragma unroll
    for (int i = 0; i < 4; i++)
        #pragma unroll
        for (int p = 0; p < 4; p++) acc[i][p] = 0;

    {
        const float* hb = hbuf + y0 * HP + x;
        #pragma unroll
        for (int t = 0; t < 14; t++) {
            const float* hr = hb + t * HP;
            u64 l0 = pk2(hr[0*PL], hr[1*PL]);   // (mu_gen, mu_ir)
            u64 l1 = pk2(hr[2*PL], hr[3*PL]);   // (mu_vis, gg)
            u64 l2 = pk2(hr[4*PL], hr[5*PL]);   // (ii, vv)
            u64 l3 = pk2(hr[6*PL], hr[7*PL]);   // (gi, gv)
            #pragma unroll
            for (int i = 0; i < 4; i++) {
                const int k = t - i;
                if (k >= 0 && k < 11) {
                    u64 w2 = wp[k];
                    acc[i][0] = fma2(w2, l0, acc[i][0]);
                    acc[i][1] = fma2(w2, l1, acc[i][1]);
                    acc[i][2] = fma2(w2, l2, acc[i][2]);
                    acc[i][3] = fma2(w2, l3, acc[i][3]);
                }
            }
        }
    }

    // ---- SSIM pointwise ----
    float acc_in = 0.0f, acc_grad = 0.0f, acc_ssim = 0.0f;
    #pragma unroll
    for (int i = 0; i < 4; i++) {
        float mu1, mu2, mu3, mgg, mii, mvv, mgi, mgv;
        upk2(acc[i][0], mu1, mu2);
        upk2(acc[i][1], mu3, mgg);
        upk2(acc[i][2], mii, mvv);
        upk2(acc[i][3], mgi, mgv);
        float s1q = mgg - mu1 * mu1;
        float s2q = mii - mu2 * mu2;
        float s3q = mvv - mu3 * mu3;
        float s12 = mgi - mu1 * mu2;
        float s13 = mgv - mu1 * mu3;
        float x2 = sqrtf(s2q), x3 = sqrtf(s3q);
        float map12 = (2.0f * s12 + C2V) / (s1q + s2q + C2V);
        float map13 = (2.0f * s13 + C2V) / (s1q + s3q + C2V);
        // NaN (sqrt of tiny-negative variance) -> cmp false -> map13, matches jnp.where
        acc_ssim += (fabsf(x2) >= fabsf(x3)) ? map12 : map13;
    }

    // ---- Sobel + L1 terms (shared 6x3 halo per image) ----
    {
        float gv[4], gi[4], gg[4];
        sobel4(sv, y0, x, gv);
        sobel4(si, y0, x, gi);
        sobel4(sg, y0, x, gg);
        #pragma unroll
        for (int i = 0; i < 4; i++) {
            int cc = (y0 + i + RAD) * IN_P + (x + RAD);
            acc_in   += fabsf(sg[cc] - fmaxf(sv[cc], si[cc]));
            acc_grad += fabsf(gg[i] - fmaxf(gv[i], gi[i]));
        }
    }

    // ---- deterministic block reduction ----
    #pragma unroll
    for (int off = 16; off; off >>= 1) {
        acc_in   += __shfl_down_sync(0xffffffffu, acc_in,   off);
        acc_grad += __shfl_down_sync(0xffffffffu, acc_grad, off);
        acc_ssim += __shfl_down_sync(0xffffffffu, acc_ssim, off);
    }
    int warp = tid >> 5, lane = tid & 31;
    if (lane == 0) { red[warp][0] = acc_in; red[warp][1] = acc_grad; red[warp][2] = acc_ssim; }
    __syncthreads();
    if (tid == 0) {
        float a = 0, b = 0, c = 0;
        #pragma unroll
        for (int w = 0; w < 8; w++) { a += red[w][0]; b += red[w][1]; c += red[w][2]; }
        int bId = (blockIdx.z * 16 + blockIdx.y) * 16 + blockIdx.x;
        g_in[bId] = a;
        g_gr[bId] = b;
        g_ss[bId] = c;
    }
}

__global__ __launch_bounds__(256)
void finalize_kernel(float* __restrict__ out)
{
    __shared__ float r0[8], r1[8], r2[8];
    const int tid = threadIdx.x;
    const float4* p0 = (const float4*)g_in;    // 2048 float4 per array
    const float4* p1 = (const float4*)g_gr;
    const float4* p2 = (const float4*)g_ss;
    float a0 = 0.0f, a1 = 0.0f, a2 = 0.0f;
    #pragma unroll
    for (int i = 0; i < 8; i++) {
        int idx = tid + i * 256;
        float4 v0 = p0[idx], v1 = p1[idx], v2 = p2[idx];
        a0 += (v0.x + v0.y) + (v0.z + v0.w);
        a1 += (v1.x + v1.y) + (v1.z + v1.w);
        a2 += (v2.x + v2.y) + (v2.z + v2.w);
    }
    #pragma unroll
    for (int off = 16; off; off >>= 1) {
        a0 += __shfl_down_sync(0xffffffffu, a0, off);
        a1 += __shfl_down_sync(0xffffffffu, a1, off);
        a2 += __shfl_down_sync(0xffffffffu, a2, off);
    }
    int warp = tid >> 5, lane = tid & 31;
    if (lane == 0) { r0[warp] = a0; r1[warp] = a1; r2[warp] = a2; }
    __syncthreads();
    if (tid == 0) {
        double t0 = 0, t1 = 0, t2 = 0;
        #pragma unroll
        for (int w = 0; w < 8; w++) {
            t0 += (double)r0[w]; t1 += (double)r1[w]; t2 += (double)r2[w];
        }
        const double tot = (double)Nimg * Hd * Wd;   // 8388608
        double loss_in   = 1.5 * t0 / tot;
        double loss_grad = t1 / tot;
        double ssim_mean = t2 / tot;
        out[0] = (float)loss_in;
        out[1] = (float)(0.5 * (1.0 - ssim_mean) + loss_grad);
    }
}

extern "C" void kernel_launch(void* const* d_in, const int* in_sizes, int n_in,
                              void* d_out, int out_size)
{
    const float* vis = (const float*)d_in[0];
    const float* ir  = (const float*)d_in[1];
    const float* gen = (const float*)d_in[2];
    float* out = (float*)d_out;

    const int SMEM_BYTES = (3 * IN_T * IN_P + 8 * IN_T * HP) * (int)sizeof(float); // 66528
    cudaFuncSetAttribute(fused_kernel, cudaFuncAttributeMaxDynamicSharedMemorySize, SMEM_BYTES);
    cudaFuncSetAttribute(fused_kernel, cudaFuncAttributePreferredSharedMemoryCarveout,
                         cudaSharedmemCarveoutMaxShared);

    dim3 grid(16, 16, 32);
    fused_kernel<<<grid, 256, SMEM_BYTES>>>(vis, ir, gen);
    finalize_kernel<<<1, 256>>>(out);
}